// round 12
// baseline (speedup 1.0000x reference)
#include <cuda_runtime.h>

typedef unsigned long long ull;

#define MD 100
#define HD 512
#define NP 10000
#define MN 51200

// ---------------- device scratch ----------------
__device__ __align__(16) float g_child0[MD*HD];
__device__ __align__(16) float g_child1[MD*HD];
__device__ __align__(16) float g_child2[MD*HD];
__device__ __align__(16) float g_A[MD*HD];
__device__ __align__(16) float g_B[MD*HD];
__device__ __align__(16) float g_Ai[MD*HD];
__device__ __align__(16) float g_Bj[MD*HD];
__device__ __align__(16) float g_h[MD*HD];
__device__ __align__(16) float g_Ce0[NP*HD];
__device__ __align__(16) float g_Ce1[NP*HD];
__device__ __align__(16) float g_gpart[4*MN];
__device__ __align__(16) float g_part[16*MN];
__device__ __align__(16) float g_partS[4*5700];
__device__ int   g_nodeok[MD];
__device__ int   g_pairlist[NP];
__device__ int   g_paircnt;

__device__ __forceinline__ ull ffma2(ull a, ull b, ull c){
    ull d;
    asm("fma.rn.f32x2 %0, %1, %2, %3;" : "=l"(d) : "l"(a), "l"(b), "l"(c));
    return d;
}
__device__ __forceinline__ ull dup2(float v){
    unsigned u = __float_as_uint(v);
    return ((ull)u << 32) | (ull)u;
}
__device__ __forceinline__ float* sel_buf(int code){
    switch (code){
        case 0: return g_A;      case 1: return g_B;
        case 2: return g_Ai;     case 3: return g_Bj;
        case 4: return g_h;      case 5: return g_child0;
        case 6: return g_child1; default: return g_child2;
    }
}
__device__ __forceinline__ float fetchA(int code, int m, int k){
    if (code == 9){   // virtual concat [child0|child1|child2]
        int q = k >> 9, kk = k & 511;
        const float* s = (q==0) ? g_child0 : (q==1) ? g_child1 : g_child2;
        return s[m*HD + kk];
    }
    return sel_buf(code)[m*HD + k];
}

// ---------------- parent GEMV: float4, split-K. grid (50,4), 256 thr ----------------
__global__ void k_gemv_part(const float* __restrict__ pf, const float* __restrict__ Wp){
    __shared__ float pfs[128];
    const int z = blockIdx.y;
    const int c4 = blockIdx.x*256 + threadIdx.x;
    if (threadIdx.x < 128) pfs[threadIdx.x] = pf[z*128 + threadIdx.x];
    __syncthreads();
    const float4* w = (const float4*)Wp + (long long)(z*128)*12800 + c4;
    float4 a = make_float4(0.f,0.f,0.f,0.f);
    #pragma unroll 8
    for (int k=0; k<128; k++){
        float4 wv = w[(long long)k*12800];
        float s = pfs[k];
        a.x += s*wv.x; a.y += s*wv.y; a.z += s*wv.z; a.w += s*wv.w;
    }
    ((float4*)g_gpart)[z*12800 + c4] = a;
}

// finisher + exists logits fused. grid 100, 128 thr.
__global__ void k_gemv_fin(const float* __restrict__ bp, const float* __restrict__ Wx,
                           const float* __restrict__ bx, float* __restrict__ out_ex){
    __shared__ float red[4];
    const int m = blockIdx.x, t = threadIdx.x;
    const int c4 = m*128 + t;
    const float4* gp = (const float4*)g_gpart;
    float4 s0 = gp[c4], s1 = gp[12800+c4], s2 = gp[2*12800+c4], s3 = gp[3*12800+c4];
    float4 b  = ((const float4*)bp)[c4];
    float4 v;
    v.x = fmaxf(s0.x+s1.x+s2.x+s3.x+b.x, 0.f);
    v.y = fmaxf(s0.y+s1.y+s2.y+s3.y+b.y, 0.f);
    v.z = fmaxf(s0.z+s1.z+s2.z+s3.z+b.z, 0.f);
    v.w = fmaxf(s0.w+s1.w+s2.w+s3.w+b.w, 0.f);
    ((float4*)g_child0)[c4] = v;
    float4 wx = ((const float4*)Wx)[t];
    float p = v.x*wx.x + v.y*wx.y + v.z*wx.z + v.w*wx.w;
    #pragma unroll
    for (int o=16; o; o>>=1) p += __shfl_xor_sync(~0u, p, o);
    if ((t & 31) == 0) red[t>>5] = p;
    __syncthreads();
    if (t == 0){
        float vv = red[0]+red[1]+red[2]+red[3] + bx[0];
        out_ex[m]   = vv;
        g_nodeok[m] = (vv > 0.f) ? 1 : 0;
        if (m == 0) g_paircnt = 0;
    }
}

// ---------------- split-K multi-job GEMM partials, pipelined ----------------
__global__ void k_gp(int acodes, int Klen, int KS,
                     const float* __restrict__ B0, const float* __restrict__ B1,
                     const float* __restrict__ B2, const float* __restrict__ B3){
    __shared__ ull   As2[16*33];
    __shared__ float Bs[16*68];
    const int KSL = Klen / KS;
    const int job = blockIdx.z / KS, sl = blockIdx.z % KS;
    const int Acode = (acodes >> (8*job)) & 255;
    const float* B = (job==0)?B0:(job==1)?B1:(job==2)?B2:B3;
    const int kb = sl*KSL;
    const int n0 = blockIdx.x*64, m0 = blockIdx.y*32;
    const int t = threadIdx.x, tr = t>>4, tc = t&15;
    const int ar0 = t>>4, ak = t&15, ar1 = ar0+16;
    const int bn = t&63, bk0 = t>>6;
    const int gm0 = m0+ar0, gm1 = m0+ar1;
    float pa0, pa1, pb0, pb1, pb2, pb3;
    {
        int k = kb + ak;
        pa0 = (gm0 < MD) ? fetchA(Acode, gm0, k) : 0.f;
        pa1 = (gm1 < MD) ? fetchA(Acode, gm1, k) : 0.f;
        int kB = kb + bk0;
        pb0 = B[(kB   )*HD + n0+bn]; pb1 = B[(kB+4 )*HD + n0+bn];
        pb2 = B[(kB+8 )*HD + n0+bn]; pb3 = B[(kB+12)*HD + n0+bn];
    }
    ull acc[2][2] = {};
    const int nkt = KSL/16;
    for (int kt=0; kt<nkt; kt++){
        As2[ak*33 + ar0] = dup2(pa0);
        As2[ak*33 + ar1] = dup2(pa1);
        Bs[(bk0   )*68 + bn] = pb0;
        Bs[(bk0+4 )*68 + bn] = pb1;
        Bs[(bk0+8 )*68 + bn] = pb2;
        Bs[(bk0+12)*68 + bn] = pb3;
        __syncthreads();
        if (kt+1 < nkt){
            int k = kb + (kt+1)*16 + ak;
            pa0 = (gm0 < MD) ? fetchA(Acode, gm0, k) : 0.f;
            pa1 = (gm1 < MD) ? fetchA(Acode, gm1, k) : 0.f;
            int kB = kb + (kt+1)*16 + bk0;
            pb0 = B[(kB   )*HD + n0+bn]; pb1 = B[(kB+4 )*HD + n0+bn];
            pb2 = B[(kB+8 )*HD + n0+bn]; pb3 = B[(kB+12)*HD + n0+bn];
        }
        #pragma unroll
        for (int k=0; k<16; k++){
            ull a0 = As2[k*33+tr], a1 = As2[k*33+tr+16];
            float4 bf = *(const float4*)&Bs[k*68 + tc*4];
            ull b0 = ((const ull*)&bf)[0], b1 = ((const ull*)&bf)[1];
            acc[0][0]=ffma2(a0,b0,acc[0][0]); acc[0][1]=ffma2(a0,b1,acc[0][1]);
            acc[1][0]=ffma2(a1,b0,acc[1][0]); acc[1][1]=ffma2(a1,b1,acc[1][1]);
        }
        __syncthreads();
    }
    float* P = g_part + (size_t)blockIdx.z*MN;
    #pragma unroll
    for (int rr=0; rr<2; rr++){
        int gm = m0 + tr + rr*16;
        if (gm < MD){
            ull* cp = (ull*)(P + gm*HD + n0 + tc*4);
            cp[0] = acc[rr][0]; cp[1] = acc[rr][1];
        }
    }
}

// sum S slices per job (float4)
__global__ void k_red(int S, int njobs, int d0, int d1, int d2, int d3){
    int i4 = blockIdx.x*256 + threadIdx.x;
    if (i4 >= njobs*12800) return;
    int job = i4 / 12800, e4 = i4 - job*12800;
    const float4* P = (const float4*)g_part;
    float4 s = make_float4(0.f,0.f,0.f,0.f);
    for (int z=0; z<S; z++){
        float4 v = P[(size_t)(job*S+z)*12800 + e4];
        s.x+=v.x; s.y+=v.y; s.z+=v.z; s.w+=v.w;
    }
    int dc = (job==0)?d0:(job==1)?d1:(job==2)?d2:d3;
    ((float4*)sel_buf(dc))[e4] = s;
}

// reduce for h with bias+relu (float4). grid 50.
__global__ void k_redh(int S, const float* __restrict__ bias){
    int i4 = blockIdx.x*256 + threadIdx.x;
    const float4* P = (const float4*)g_part;
    float4 s = make_float4(0.f,0.f,0.f,0.f);
    for (int z=0; z<S; z++){
        float4 v = P[(size_t)z*12800 + i4];
        s.x+=v.x; s.y+=v.y; s.z+=v.z; s.w+=v.w;
    }
    float4 b = ((const float4*)bias)[i4 & 127];
    s.x = fmaxf(s.x+b.x,0.f); s.y = fmaxf(s.y+b.y,0.f);
    s.z = fmaxf(s.z+b.z,0.f); s.w = fmaxf(s.w+b.w,0.f);
    ((float4*)g_h)[i4] = s;
}

// ---------------- edge logits + pair compaction. grid (100,13), 256 thr ----------------
__global__ void k_el(const float* __restrict__ bel, const float* __restrict__ Wee,
                     const float* __restrict__ bee, float* __restrict__ out_lg){
    __shared__ float sWee[4*HD];
    __shared__ float sbel[HD];
    const int t = threadIdx.x;
    #pragma unroll
    for (int q=0; q<8; q++) sWee[t + q*256] = Wee[t + q*256];
    sbel[t] = bel[t]; sbel[t+256] = bel[t+256];
    __syncthreads();
    const int i = blockIdx.x;
    const int w = t >> 5, lane = t & 31;
    const int j = blockIdx.y*8 + w;
    if (j >= MD) return;
    const float* Ar = g_A + i*HD;
    const float* Br = g_B + j*HD;
    float p0=0.f, p1=0.f, p2=0.f, p3=0.f;
    #pragma unroll
    for (int s=0; s<16; s++){
        int h = lane + s*32;
        float v = fmaxf(Ar[h] + Br[h] + sbel[h], 0.f);
        p0 += v*sWee[h]; p1 += v*sWee[HD+h]; p2 += v*sWee[2*HD+h]; p3 += v*sWee[3*HD+h];
    }
    #pragma unroll
    for (int o=16; o; o>>=1){
        p0 += __shfl_xor_sync(~0u, p0, o);
        p1 += __shfl_xor_sync(~0u, p1, o);
        p2 += __shfl_xor_sync(~0u, p2, o);
        p3 += __shfl_xor_sync(~0u, p3, o);
    }
    if (lane == 0){
        p0 += bee[0]; p1 += bee[1]; p2 += bee[2]; p3 += bee[3];
        int p = i*MD + j;
        *(float4*)(out_lg + p*4) = make_float4(p0, p1, p2, p3);
        if (g_nodeok[i] && g_nodeok[j] && (p0>0.f || p1>0.f || p2>0.f || p3>0.f)){
            int pos = atomicAdd(&g_paircnt, 1);
            g_pairlist[pos] = p;
        }
    }
}

// ---------------- gathered edge GEMM, BOTH iterations fused. grid (8,157), 256 thr ----------------
// Vectorized loaders: A-gather 2x LDG.128/thread/tile, B 1x LDG.128 + 1x STS.128 per matrix.
// A-smem: pre-duplicated ull, stride 66; reads are 2 broadcast LDS.128 per k.
__global__ void __launch_bounds__(256,3)
k_ce(const float* __restrict__ We0, const float* __restrict__ We1,
     const float* __restrict__ bel){
    __shared__ int   pp[64], pi[64], pj[64];
    __shared__ float sbel[HD];
    __shared__ __align__(16) ull As2[16*66];
    __shared__ __align__(16) float Bs0[16*68];
    __shared__ __align__(16) float Bs1[16*68];
    const int cnt = g_paircnt;
    const int m0  = blockIdx.y*64;
    if (m0 >= cnt) return;
    const int n0 = blockIdx.x*64;
    const int t = threadIdx.x;
    if (t < 64){
        int p = (m0 + t < cnt) ? g_pairlist[m0 + t] : g_pairlist[m0];
        pp[t] = p; pi[t] = (p/MD)*HD; pj[t] = (p%MD)*HD;
    }
    sbel[t] = bel[t]; sbel[t+256] = bel[t+256];
    __syncthreads();
    const int tr = t>>4, tc = t&15;
    // A loader: thread owns row lr (0..63) and 4 consecutive k (lk4..lk4+3)
    const int lr  = t & 63, lk4 = (t >> 6)*4;
    // B loader: thread owns k-row bk (0..15) and 4 consecutive n (bn4..bn4+3)
    const int bk  = t >> 4, bn4 = (t & 15)*4;
    const int piR = pi[lr], pjR = pj[lr];
    float4 va, vb, w0, w1;
    va = *(const float4*)&g_A[piR + lk4];
    vb = *(const float4*)&g_B[pjR + lk4];
    w0 = *(const float4*)&We0[bk*HD + n0 + bn4];
    w1 = *(const float4*)&We1[bk*HD + n0 + bn4];
    ull acc0[4][2] = {}, acc1[4][2] = {};
    for (int kt=0; kt<32; kt++){
        {
            const int kb = kt*16;
            As2[(lk4  )*66 + lr] = dup2(fmaxf(va.x + vb.x + sbel[kb + lk4    ], 0.f));
            As2[(lk4+1)*66 + lr] = dup2(fmaxf(va.y + vb.y + sbel[kb + lk4 + 1], 0.f));
            As2[(lk4+2)*66 + lr] = dup2(fmaxf(va.z + vb.z + sbel[kb + lk4 + 2], 0.f));
            As2[(lk4+3)*66 + lr] = dup2(fmaxf(va.w + vb.w + sbel[kb + lk4 + 3], 0.f));
            *(float4*)&Bs0[bk*68 + bn4] = w0;
            *(float4*)&Bs1[bk*68 + bn4] = w1;
        }
        __syncthreads();
        if (kt+1 < 32){
            int ko = (kt+1)*16;
            va = *(const float4*)&g_A[piR + ko + lk4];
            vb = *(const float4*)&g_B[pjR + ko + lk4];
            w0 = *(const float4*)&We0[(ko + bk)*HD + n0 + bn4];
            w1 = *(const float4*)&We1[(ko + bk)*HD + n0 + bn4];
        }
        #pragma unroll
        for (int k=0; k<16; k++){
            ulonglong2 aa0 = *(const ulonglong2*)&As2[k*66 + tr*4];
            ulonglong2 aa1 = *(const ulonglong2*)&As2[k*66 + tr*4 + 2];
            ull a0 = aa0.x, a1 = aa0.y, a2 = aa1.x, a3 = aa1.y;
            float4 b0f = *(const float4*)&Bs0[k*68 + tc*4];
            float4 b1f = *(const float4*)&Bs1[k*68 + tc*4];
            ull p0 = ((const ull*)&b0f)[0], p1 = ((const ull*)&b0f)[1];
            ull q0 = ((const ull*)&b1f)[0], q1 = ((const ull*)&b1f)[1];
            acc0[0][0]=ffma2(a0,p0,acc0[0][0]); acc0[0][1]=ffma2(a0,p1,acc0[0][1]);
            acc0[1][0]=ffma2(a1,p0,acc0[1][0]); acc0[1][1]=ffma2(a1,p1,acc0[1][1]);
            acc0[2][0]=ffma2(a2,p0,acc0[2][0]); acc0[2][1]=ffma2(a2,p1,acc0[2][1]);
            acc0[3][0]=ffma2(a3,p0,acc0[3][0]); acc0[3][1]=ffma2(a3,p1,acc0[3][1]);
            acc1[0][0]=ffma2(a0,q0,acc1[0][0]); acc1[0][1]=ffma2(a0,q1,acc1[0][1]);
            acc1[1][0]=ffma2(a1,q0,acc1[1][0]); acc1[1][1]=ffma2(a1,q1,acc1[1][1]);
            acc1[2][0]=ffma2(a2,q0,acc1[2][0]); acc1[2][1]=ffma2(a2,q1,acc1[2][1]);
            acc1[3][0]=ffma2(a3,q0,acc1[3][0]); acc1[3][1]=ffma2(a3,q1,acc1[3][1]);
        }
        __syncthreads();
    }
    #pragma unroll
    for (int q=0; q<4; q++){
        int rl = tr*4 + q;                 // consecutive rows per thread
        if (m0 + rl < cnt){
            int off = pp[rl]*HD + n0 + tc*4;
            ull* c0 = (ull*)(g_Ce0 + off);
            c0[0] = acc0[q][0]; c0[1] = acc0[q][1];
            ull* c1 = (ull*)(g_Ce1 + off);
            c1[0] = acc1[q][0]; c1[1] = acc1[q][1];
        }
    }
}

// ---------------- message pass + scatter-sum. grid 100, 512 thr, 2-deep prefetch ----------------
__global__ void k_msg(int it, const float* __restrict__ lgg,
                      const float* __restrict__ Wt, const float* __restrict__ bne){
    __shared__ float lg[400];
    __shared__ int   jl[100];
    __shared__ int   njl;
    const float* childin  = it ? g_child1 : g_child0;
    float*       childout = it ? g_child2 : g_child1;
    const float* Ce       = it ? g_Ce1    : g_Ce0;
    const int i = blockIdx.x, h = threadIdx.x;
    if (h < 400) lg[h] = lgg[i*400 + h];
    __syncthreads();
    if (h == 0){
        int n = 0;
        if (g_nodeok[i]){
            for (int j=0; j<MD; j++){
                if (!g_nodeok[j]) continue;
                if (lg[j*4]>0.f || lg[j*4+1]>0.f || lg[j*4+2]>0.f || lg[j*4+3]>0.f) jl[n++] = j;
            }
        }
        njl = n;
    }
    __syncthreads();
    float cin = childin[i*HD + h];
    bool any = (g_paircnt > 0);
    float acc = 0.f;
    const int n = njl;
    float base_i = g_Ai[i*HD + h] + bne[h];
    float wt0 = Wt[h], wt1 = Wt[HD+h], wt2 = Wt[2*HD+h], wt3 = Wt[3*HD+h];
    const float* CeI = Ce + (long long)i*MD*HD;
    float bA=0.f, cA=0.f, bB=0.f, cB=0.f;
    if (n > 0){ int j0 = jl[0]; bA = g_Bj[j0*HD+h]; cA = CeI[j0*HD+h]; }
    if (n > 1){ int j1 = jl[1]; bB = g_Bj[j1*HD+h]; cB = CeI[j1*HD+h]; }
    for (int q=0; q<n; q++){
        int j = jl[q];
        float cb = bA, cc = cA;
        bA = bB; cA = cB;
        if (q+2 < n){
            int jn = jl[q+2];
            bB = g_Bj[jn*HD + h]; cB = CeI[jn*HD + h];
        }
        float l0 = lg[j*4], l1 = lg[j*4+1], l2 = lg[j*4+2], l3 = lg[j*4+3];
        float base = base_i + cb + cc;
        if (l0 > 0.f) acc += fmaxf(fmaf(l0, wt0, base), 0.f);
        if (l1 > 0.f) acc += fmaxf(fmaf(l1, wt1, base), 0.f);
        if (l2 > 0.f) acc += fmaxf(fmaf(l2, wt2, base), 0.f);
        if (l3 > 0.f) acc += fmaxf(fmaf(l3, wt3, base), 0.f);
    }
    childout[i*HD + h] = any ? acc : cin;
}

// ---------------- heads partials: x<8 child2 (N=512), x==8 sem (N=57). grid (9,4,4) ----------------
__global__ void k_heads(const float* __restrict__ Wc2, const float* __restrict__ Ws){
    __shared__ ull   As2[16*33];
    __shared__ float Bs[16*68];
    const bool semjob = (blockIdx.x == 8);
    const float* B = semjob ? Ws : Wc2;
    const int N   = semjob ? 57 : 512;
    const int n0  = semjob ? 0  : blockIdx.x*64;
    const int m0  = blockIdx.y*32;
    const int kb  = blockIdx.z*128;
    const int t = threadIdx.x, tr = t>>4, tc = t&15;
    const int ar0 = t>>4, ak = t&15, ar1 = ar0+16;
    const int bn = t&63, bk0 = t>>6;
    const int gm0 = m0+ar0, gm1 = m0+ar1;
    const bool bok = (n0 + bn) < N;
    float pa0, pa1, pb0, pb1, pb2, pb3;
    {
        int k = kb + ak;
        pa0 = (gm0 < MD) ? g_h[gm0*HD + k] : 0.f;
        pa1 = (gm1 < MD) ? g_h[gm1*HD + k] : 0.f;
        int kB = kb + bk0;
        pb0 = bok ? B[(kB   )*N + n0+bn] : 0.f;
        pb1 = bok ? B[(kB+4 )*N + n0+bn] : 0.f;
        pb2 = bok ? B[(kB+8 )*N + n0+bn] : 0.f;
        pb3 = bok ? B[(kB+12)*N + n0+bn] : 0.f;
    }
    ull acc[2][2] = {};
    for (int kt=0; kt<8; kt++){
        As2[ak*33 + ar0] = dup2(pa0);
        As2[ak*33 + ar1] = dup2(pa1);
        Bs[(bk0   )*68 + bn] = pb0;
        Bs[(bk0+4 )*68 + bn] = pb1;
        Bs[(bk0+8 )*68 + bn] = pb2;
        Bs[(bk0+12)*68 + bn] = pb3;
        __syncthreads();
        if (kt+1 < 8){
            int k = kb + (kt+1)*16 + ak;
            pa0 = (gm0 < MD) ? g_h[gm0*HD + k] : 0.f;
            pa1 = (gm1 < MD) ? g_h[gm1*HD + k] : 0.f;
            int kB = kb + (kt+1)*16 + bk0;
            pb0 = bok ? B[(kB   )*N + n0+bn] : 0.f;
            pb1 = bok ? B[(kB+4 )*N + n0+bn] : 0.f;
            pb2 = bok ? B[(kB+8 )*N + n0+bn] : 0.f;
            pb3 = bok ? B[(kB+12)*N + n0+bn] : 0.f;
        }
        #pragma unroll
        for (int k=0; k<16; k++){
            ull a0 = As2[k*33+tr], a1 = As2[k*33+tr+16];
            float4 bf = *(const float4*)&Bs[k*68 + tc*4];
            ull b0 = ((const ull*)&bf)[0], b1 = ((const ull*)&bf)[1];
            acc[0][0]=ffma2(a0,b0,acc[0][0]); acc[0][1]=ffma2(a0,b1,acc[0][1]);
            acc[1][0]=ffma2(a1,b0,acc[1][0]); acc[1][1]=ffma2(a1,b1,acc[1][1]);
        }
        __syncthreads();
    }
    const int sl = blockIdx.z;
    #pragma unroll
    for (int rr=0; rr<2; rr++){
        int gm = m0 + tr + rr*16;
        if (gm >= MD) continue;
        float r0 = __uint_as_float((unsigned)(acc[rr][0]      ));
        float r1 = __uint_as_float((unsigned)(acc[rr][0] >> 32));
        float r2 = __uint_as_float((unsigned)(acc[rr][1]      ));
        float r3 = __uint_as_float((unsigned)(acc[rr][1] >> 32));
        int gn = n0 + tc*4;
        if (!semjob){
            ull* cp = (ull*)(g_part + (size_t)sl*MN + gm*HD + gn);
            cp[0] = acc[rr][0]; cp[1] = acc[rr][1];
        } else {
            float* P = g_partS + sl*5700 + gm*57;
            if (gn   < 57) P[gn  ] = r0;
            if (gn+1 < 57) P[gn+1] = r1;
            if (gn+2 < 57) P[gn+2] = r2;
            if (gn+3 < 57) P[gn+3] = r3;
        }
    }
}

// final output reduce. blocks 0..49: child_out float4, 50..72: sem scalar.
__global__ void k_out(const float* __restrict__ bc2, const float* __restrict__ bs,
                      float* __restrict__ out_co, float* __restrict__ out_sem){
    if (blockIdx.x < 50){
        int i4 = blockIdx.x*256 + threadIdx.x;
        const float4* P = (const float4*)g_part;
        float4 s = make_float4(0.f,0.f,0.f,0.f);
        #pragma unroll
        for (int z=0; z<4; z++){
            float4 v = P[(size_t)z*12800 + i4];
            s.x+=v.x; s.y+=v.y; s.z+=v.z; s.w+=v.w;
        }
        float4 b = ((const float4*)bc2)[i4 & 127];
        s.x = fmaxf(s.x+b.x,0.f); s.y = fmaxf(s.y+b.y,0.f);
        s.z = fmaxf(s.z+b.z,0.f); s.w = fmaxf(s.w+b.w,0.f);
        ((float4*)out_co)[i4] = s;
    } else {
        int e = (blockIdx.x-50)*256 + threadIdx.x;
        if (e >= 5700) return;
        float s = 0.f;
        #pragma unroll
        for (int z=0; z<4; z++) s += g_partS[z*5700 + e];
        out_sem[e] = s + bs[e % 57];
    }
}

// ---------------- launch ----------------
extern "C" void kernel_launch(void* const* d_in, const int* in_sizes, int n_in,
                              void* d_out, int out_size){
    const float* pf  = (const float*)d_in[0];
    const float* Wp  = (const float*)d_in[1];
    const float* bp  = (const float*)d_in[2];
    const float* Wx  = (const float*)d_in[3];
    const float* bx  = (const float*)d_in[4];
    const float* Wel = (const float*)d_in[5];
    const float* bel = (const float*)d_in[6];
    const float* Wee = (const float*)d_in[7];
    const float* bee = (const float*)d_in[8];
    const float* Wne = (const float*)d_in[9];
    const float* bne = (const float*)d_in[10];
    const float* Wc  = (const float*)d_in[11];
    const float* bc  = (const float*)d_in[12];
    const float* Ws  = (const float*)d_in[13];
    const float* bs  = (const float*)d_in[14];
    const float* Wc2 = (const float*)d_in[15];
    const float* bc2 = (const float*)d_in[16];

    float* out     = (float*)d_out;
    float* out_co  = out;
    float* out_sem = out + 51200;
    float* out_ex  = out + 56900;
    float* out_lg  = out + 57000;

    k_gemv_part<<<dim3(50,4),256>>>(pf, Wp);
    k_gemv_fin<<<100,128>>>(bp, Wx, bx, out_ex);
    k_gp<<<dim3(8,4,16),256>>>(5 | (5<<8) | (5<<16) | (5<<24), 512, 4,
                               Wel, Wel + 512*512, Wne, Wne + 512*512);
    k_red<<<200,256>>>(4, 4, 0, 1, 2, 3);
    k_el<<<dim3(100,13),256>>>(bel, Wee, bee, out_lg);
    k_ce<<<dim3(8,157),256>>>(Wne + 1024*512, Wne + (1540+1024)*512, bel);
    k_msg<<<100,512>>>(0, out_lg, Wne + 1536*512, bne);
    k_gp<<<dim3(8,4,8),256>>>(6 | (6<<8), 512, 4,
                              Wne + 1540*512, Wne + (1540+512)*512, Wne, Wne);
    k_red<<<100,256>>>(4, 2, 2, 3, 0, 0);
    k_msg<<<100,512>>>(1, out_lg, Wne + (1540+1536)*512, bne + 512);
    k_gp<<<dim3(8,4,8),256>>>(9, 1536, 8, Wc, Wc, Wc, Wc);
    k_redh<<<50,256>>>(8, bc);
    k_heads<<<dim3(9,4,4),256>>>(Wc2, Ws);
    k_out<<<73,256>>>(bc2, bs, out_co, out_sem);
}

// round 13
// speedup vs baseline: 1.0571x; 1.0571x over previous
#include <cuda_runtime.h>

typedef unsigned long long ull;

#define MD 100
#define HD 512
#define NP 10000
#define MN 51200

// ---------------- device scratch ----------------
__device__ __align__(16) float g_child0[MD*HD];
__device__ __align__(16) float g_child1[MD*HD];
__device__ __align__(16) float g_child2[MD*HD];
__device__ __align__(16) float g_A[MD*HD];
__device__ __align__(16) float g_B[MD*HD];
__device__ __align__(16) float g_Ai[MD*HD];
__device__ __align__(16) float g_Bj[MD*HD];
__device__ __align__(16) float g_Ce0[NP*HD];
__device__ __align__(16) float g_Ce1[NP*HD];
__device__ __align__(16) float g_gpart[4*MN];
__device__ __align__(16) float g_part[16*MN];
__device__ __align__(16) float g_partS[4*5700];
__device__ int   g_nodeok[MD];
__device__ int   g_pairlist[NP];
__device__ int   g_paircnt;

__device__ __forceinline__ ull ffma2(ull a, ull b, ull c){
    ull d;
    asm("fma.rn.f32x2 %0, %1, %2, %3;" : "=l"(d) : "l"(a), "l"(b), "l"(c));
    return d;
}
__device__ __forceinline__ ull dup2(float v){
    unsigned u = __float_as_uint(v);
    return ((ull)u << 32) | (ull)u;
}
__device__ __forceinline__ float* sel_buf(int code){
    switch (code){
        case 0: return g_A;      case 1: return g_B;
        case 2: return g_Ai;     case 3: return g_Bj;
        case 4: return g_part;   case 5: return g_child0;
        case 6: return g_child1; default: return g_child2;
    }
}
__device__ __forceinline__ float fetchA(int code, int m, int k){
    if (code == 9){   // virtual concat [child0|child1|child2]
        int q = k >> 9, kk = k & 511;
        const float* s = (q==0) ? g_child0 : (q==1) ? g_child1 : g_child2;
        return s[m*HD + kk];
    }
    return sel_buf(code)[m*HD + k];
}

// ---------------- parent GEMV: float4, split-K. grid (50,4), 256 thr ----------------
__global__ void k_gemv_part(const float* __restrict__ pf, const float* __restrict__ Wp){
    __shared__ float pfs[128];
    const int z = blockIdx.y;
    const int c4 = blockIdx.x*256 + threadIdx.x;
    if (threadIdx.x < 128) pfs[threadIdx.x] = pf[z*128 + threadIdx.x];
    __syncthreads();
    const float4* w = (const float4*)Wp + (long long)(z*128)*12800 + c4;
    float4 a = make_float4(0.f,0.f,0.f,0.f);
    #pragma unroll 8
    for (int k=0; k<128; k++){
        float4 wv = w[(long long)k*12800];
        float s = pfs[k];
        a.x += s*wv.x; a.y += s*wv.y; a.z += s*wv.z; a.w += s*wv.w;
    }
    ((float4*)g_gpart)[z*12800 + c4] = a;
}

// finisher + exists logits fused. grid 100, 128 thr.
__global__ void k_gemv_fin(const float* __restrict__ bp, const float* __restrict__ Wx,
                           const float* __restrict__ bx, float* __restrict__ out_ex){
    __shared__ float red[4];
    const int m = blockIdx.x, t = threadIdx.x;
    const int c4 = m*128 + t;
    const float4* gp = (const float4*)g_gpart;
    float4 s0 = gp[c4], s1 = gp[12800+c4], s2 = gp[2*12800+c4], s3 = gp[3*12800+c4];
    float4 b  = ((const float4*)bp)[c4];
    float4 v;
    v.x = fmaxf(s0.x+s1.x+s2.x+s3.x+b.x, 0.f);
    v.y = fmaxf(s0.y+s1.y+s2.y+s3.y+b.y, 0.f);
    v.z = fmaxf(s0.z+s1.z+s2.z+s3.z+b.z, 0.f);
    v.w = fmaxf(s0.w+s1.w+s2.w+s3.w+b.w, 0.f);
    ((float4*)g_child0)[c4] = v;
    float4 wx = ((const float4*)Wx)[t];
    float p = v.x*wx.x + v.y*wx.y + v.z*wx.z + v.w*wx.w;
    #pragma unroll
    for (int o=16; o; o>>=1) p += __shfl_xor_sync(~0u, p, o);
    if ((t & 31) == 0) red[t>>5] = p;
    __syncthreads();
    if (t == 0){
        float vv = red[0]+red[1]+red[2]+red[3] + bx[0];
        out_ex[m]   = vv;
        g_nodeok[m] = (vv > 0.f) ? 1 : 0;
        if (m == 0) g_paircnt = 0;
    }
}

// ---------------- split-K multi-job GEMM partials, pipelined ----------------
__global__ void k_gp(int acodes, int Klen, int KS,
                     const float* __restrict__ B0, const float* __restrict__ B1,
                     const float* __restrict__ B2, const float* __restrict__ B3){
    __shared__ ull   As2[16*33];
    __shared__ float Bs[16*68];
    const int KSL = Klen / KS;
    const int job = blockIdx.z / KS, sl = blockIdx.z % KS;
    const int Acode = (acodes >> (8*job)) & 255;
    const float* B = (job==0)?B0:(job==1)?B1:(job==2)?B2:B3;
    const int kb = sl*KSL;
    const int n0 = blockIdx.x*64, m0 = blockIdx.y*32;
    const int t = threadIdx.x, tr = t>>4, tc = t&15;
    const int ar0 = t>>4, ak = t&15, ar1 = ar0+16;
    const int bn = t&63, bk0 = t>>6;
    const int gm0 = m0+ar0, gm1 = m0+ar1;
    float pa0, pa1, pb0, pb1, pb2, pb3;
    {
        int k = kb + ak;
        pa0 = (gm0 < MD) ? fetchA(Acode, gm0, k) : 0.f;
        pa1 = (gm1 < MD) ? fetchA(Acode, gm1, k) : 0.f;
        int kB = kb + bk0;
        pb0 = B[(kB   )*HD + n0+bn]; pb1 = B[(kB+4 )*HD + n0+bn];
        pb2 = B[(kB+8 )*HD + n0+bn]; pb3 = B[(kB+12)*HD + n0+bn];
    }
    ull acc[2][2] = {};
    const int nkt = KSL/16;
    for (int kt=0; kt<nkt; kt++){
        As2[ak*33 + ar0] = dup2(pa0);
        As2[ak*33 + ar1] = dup2(pa1);
        Bs[(bk0   )*68 + bn] = pb0;
        Bs[(bk0+4 )*68 + bn] = pb1;
        Bs[(bk0+8 )*68 + bn] = pb2;
        Bs[(bk0+12)*68 + bn] = pb3;
        __syncthreads();
        if (kt+1 < nkt){
            int k = kb + (kt+1)*16 + ak;
            pa0 = (gm0 < MD) ? fetchA(Acode, gm0, k) : 0.f;
            pa1 = (gm1 < MD) ? fetchA(Acode, gm1, k) : 0.f;
            int kB = kb + (kt+1)*16 + bk0;
            pb0 = B[(kB   )*HD + n0+bn]; pb1 = B[(kB+4 )*HD + n0+bn];
            pb2 = B[(kB+8 )*HD + n0+bn]; pb3 = B[(kB+12)*HD + n0+bn];
        }
        #pragma unroll
        for (int k=0; k<16; k++){
            ull a0 = As2[k*33+tr], a1 = As2[k*33+tr+16];
            float4 bf = *(const float4*)&Bs[k*68 + tc*4];
            ull b0 = ((const ull*)&bf)[0], b1 = ((const ull*)&bf)[1];
            acc[0][0]=ffma2(a0,b0,acc[0][0]); acc[0][1]=ffma2(a0,b1,acc[0][1]);
            acc[1][0]=ffma2(a1,b0,acc[1][0]); acc[1][1]=ffma2(a1,b1,acc[1][1]);
        }
        __syncthreads();
    }
    float* P = g_part + (size_t)blockIdx.z*MN;
    #pragma unroll
    for (int rr=0; rr<2; rr++){
        int gm = m0 + tr + rr*16;
        if (gm < MD){
            ull* cp = (ull*)(P + gm*HD + n0 + tc*4);
            cp[0] = acc[rr][0]; cp[1] = acc[rr][1];
        }
    }
}

// sum S slices per job (float4)
__global__ void k_red(int S, int njobs, int d0, int d1, int d2, int d3){
    int i4 = blockIdx.x*256 + threadIdx.x;
    if (i4 >= njobs*12800) return;
    int job = i4 / 12800, e4 = i4 - job*12800;
    const float4* P = (const float4*)g_part;
    float4 s = make_float4(0.f,0.f,0.f,0.f);
    for (int z=0; z<S; z++){
        float4 v = P[(size_t)(job*S+z)*12800 + e4];
        s.x+=v.x; s.y+=v.y; s.z+=v.z; s.w+=v.w;
    }
    int dc = (job==0)?d0:(job==1)?d1:(job==2)?d2:d3;
    ((float4*)sel_buf(dc))[e4] = s;
}

// ---------------- edge logits + pair compaction. grid (100,13), 256 thr ----------------
__global__ void k_el(const float* __restrict__ bel, const float* __restrict__ Wee,
                     const float* __restrict__ bee, float* __restrict__ out_lg){
    __shared__ float sWee[4*HD];
    __shared__ float sbel[HD];
    const int t = threadIdx.x;
    #pragma unroll
    for (int q=0; q<8; q++) sWee[t + q*256] = Wee[t + q*256];
    sbel[t] = bel[t]; sbel[t+256] = bel[t+256];
    __syncthreads();
    const int i = blockIdx.x;
    const int w = t >> 5, lane = t & 31;
    const int j = blockIdx.y*8 + w;
    if (j >= MD) return;
    const float* Ar = g_A + i*HD;
    const float* Br = g_B + j*HD;
    float p0=0.f, p1=0.f, p2=0.f, p3=0.f;
    #pragma unroll
    for (int s=0; s<16; s++){
        int h = lane + s*32;
        float v = fmaxf(Ar[h] + Br[h] + sbel[h], 0.f);
        p0 += v*sWee[h]; p1 += v*sWee[HD+h]; p2 += v*sWee[2*HD+h]; p3 += v*sWee[3*HD+h];
    }
    #pragma unroll
    for (int o=16; o; o>>=1){
        p0 += __shfl_xor_sync(~0u, p0, o);
        p1 += __shfl_xor_sync(~0u, p1, o);
        p2 += __shfl_xor_sync(~0u, p2, o);
        p3 += __shfl_xor_sync(~0u, p3, o);
    }
    if (lane == 0){
        p0 += bee[0]; p1 += bee[1]; p2 += bee[2]; p3 += bee[3];
        int p = i*MD + j;
        *(float4*)(out_lg + p*4) = make_float4(p0, p1, p2, p3);
        if (g_nodeok[i] && g_nodeok[j] && (p0>0.f || p1>0.f || p2>0.f || p3>0.f)){
            int pos = atomicAdd(&g_paircnt, 1);
            g_pairlist[pos] = p;
        }
    }
}

// ---------------- gathered edge GEMM, BOTH iterations fused. grid (8,157), 256 thr ----------------
// Vectorized loaders + explicit register double-buffering of LDS fragments:
// the 16 FFMA2s of step k overlap the LDS of step k+1.
__global__ void __launch_bounds__(256,2)
k_ce(const float* __restrict__ We0, const float* __restrict__ We1,
     const float* __restrict__ bel){
    __shared__ int   pp[64], pi[64], pj[64];
    __shared__ float sbel[HD];
    __shared__ __align__(16) ull As2[16*66];
    __shared__ __align__(16) float Bs0[16*68];
    __shared__ __align__(16) float Bs1[16*68];
    const int cnt = g_paircnt;
    const int m0  = blockIdx.y*64;
    if (m0 >= cnt) return;
    const int n0 = blockIdx.x*64;
    const int t = threadIdx.x;
    if (t < 64){
        int p = (m0 + t < cnt) ? g_pairlist[m0 + t] : g_pairlist[m0];
        pp[t] = p; pi[t] = (p/MD)*HD; pj[t] = (p%MD)*HD;
    }
    sbel[t] = bel[t]; sbel[t+256] = bel[t+256];
    __syncthreads();
    const int tr = t>>4, tc = t&15;
    const int lr  = t & 63, lk4 = (t >> 6)*4;       // A loader: row, 4 consecutive k
    const int bk  = t >> 4, bn4 = (t & 15)*4;       // B loader: k-row, 4 consecutive n
    const int piR = pi[lr], pjR = pj[lr];
    float4 va, vb, w0, w1;
    va = *(const float4*)&g_A[piR + lk4];
    vb = *(const float4*)&g_B[pjR + lk4];
    w0 = *(const float4*)&We0[bk*HD + n0 + bn4];
    w1 = *(const float4*)&We1[bk*HD + n0 + bn4];
    ull acc0[4][2] = {}, acc1[4][2] = {};
    for (int kt=0; kt<32; kt++){
        {
            const int kb2 = kt*16;
            As2[(lk4  )*66 + lr] = dup2(fmaxf(va.x + vb.x + sbel[kb2 + lk4    ], 0.f));
            As2[(lk4+1)*66 + lr] = dup2(fmaxf(va.y + vb.y + sbel[kb2 + lk4 + 1], 0.f));
            As2[(lk4+2)*66 + lr] = dup2(fmaxf(va.z + vb.z + sbel[kb2 + lk4 + 2], 0.f));
            As2[(lk4+3)*66 + lr] = dup2(fmaxf(va.w + vb.w + sbel[kb2 + lk4 + 3], 0.f));
            *(float4*)&Bs0[bk*68 + bn4] = w0;
            *(float4*)&Bs1[bk*68 + bn4] = w1;
        }
        __syncthreads();
        if (kt+1 < 32){
            int ko = (kt+1)*16;
            va = *(const float4*)&g_A[piR + ko + lk4];
            vb = *(const float4*)&g_B[pjR + ko + lk4];
            w0 = *(const float4*)&We0[(ko + bk)*HD + n0 + bn4];
            w1 = *(const float4*)&We1[(ko + bk)*HD + n0 + bn4];
        }
        // register-double-buffered fragment pipeline over k=0..15
        ulonglong2 A0c = *(const ulonglong2*)&As2[tr*4];
        ulonglong2 A1c = *(const ulonglong2*)&As2[tr*4 + 2];
        float4 B0c = *(const float4*)&Bs0[tc*4];
        float4 B1c = *(const float4*)&Bs1[tc*4];
        #pragma unroll
        for (int k=0; k<16; k++){
            ulonglong2 A0n, A1n; float4 B0n, B1n;
            if (k < 15){
                A0n = *(const ulonglong2*)&As2[(k+1)*66 + tr*4];
                A1n = *(const ulonglong2*)&As2[(k+1)*66 + tr*4 + 2];
                B0n = *(const float4*)&Bs0[(k+1)*68 + tc*4];
                B1n = *(const float4*)&Bs1[(k+1)*68 + tc*4];
            }
            ull a0 = A0c.x, a1 = A0c.y, a2 = A1c.x, a3 = A1c.y;
            ull p0 = ((const ull*)&B0c)[0], p1 = ((const ull*)&B0c)[1];
            ull q0 = ((const ull*)&B1c)[0], q1 = ((const ull*)&B1c)[1];
            acc0[0][0]=ffma2(a0,p0,acc0[0][0]); acc0[0][1]=ffma2(a0,p1,acc0[0][1]);
            acc0[1][0]=ffma2(a1,p0,acc0[1][0]); acc0[1][1]=ffma2(a1,p1,acc0[1][1]);
            acc0[2][0]=ffma2(a2,p0,acc0[2][0]); acc0[2][1]=ffma2(a2,p1,acc0[2][1]);
            acc0[3][0]=ffma2(a3,p0,acc0[3][0]); acc0[3][1]=ffma2(a3,p1,acc0[3][1]);
            acc1[0][0]=ffma2(a0,q0,acc1[0][0]); acc1[0][1]=ffma2(a0,q1,acc1[0][1]);
            acc1[1][0]=ffma2(a1,q0,acc1[1][0]); acc1[1][1]=ffma2(a1,q1,acc1[1][1]);
            acc1[2][0]=ffma2(a2,q0,acc1[2][0]); acc1[2][1]=ffma2(a2,q1,acc1[2][1]);
            acc1[3][0]=ffma2(a3,q0,acc1[3][0]); acc1[3][1]=ffma2(a3,q1,acc1[3][1]);
            if (k < 15){ A0c = A0n; A1c = A1n; B0c = B0n; B1c = B1n; }
        }
        __syncthreads();
    }
    #pragma unroll
    for (int q=0; q<4; q++){
        int rl = tr*4 + q;
        if (m0 + rl < cnt){
            int off = pp[rl]*HD + n0 + tc*4;
            ull* c0 = (ull*)(g_Ce0 + off);
            c0[0] = acc0[q][0]; c0[1] = acc0[q][1];
            ull* c1 = (ull*)(g_Ce1 + off);
            c1[0] = acc1[q][0]; c1[1] = acc1[q][1];
        }
    }
}

// ---------------- message pass + scatter-sum. grid 100, 512 thr, 4-deep prefetch ----------------
__global__ void k_msg(int it, const float* __restrict__ lgg,
                      const float* __restrict__ Wt, const float* __restrict__ bne){
    __shared__ float lg[400];
    __shared__ int   jl[100];
    __shared__ int   njl;
    const float* childin  = it ? g_child1 : g_child0;
    float*       childout = it ? g_child2 : g_child1;
    const float* Ce       = it ? g_Ce1    : g_Ce0;
    const int i = blockIdx.x, h = threadIdx.x;
    if (h < 400) lg[h] = lgg[i*400 + h];
    __syncthreads();
    if (h == 0){
        int n = 0;
        if (g_nodeok[i]){
            for (int j=0; j<MD; j++){
                if (!g_nodeok[j]) continue;
                if (lg[j*4]>0.f || lg[j*4+1]>0.f || lg[j*4+2]>0.f || lg[j*4+3]>0.f) jl[n++] = j;
            }
        }
        njl = n;
    }
    __syncthreads();
    float cin = childin[i*HD + h];
    bool any = (g_paircnt > 0);
    float acc = 0.f;
    const int n = njl;
    float base_i = g_Ai[i*HD + h] + bne[h];
    float wt0 = Wt[h], wt1 = Wt[HD+h], wt2 = Wt[2*HD+h], wt3 = Wt[3*HD+h];
    const float* CeI = Ce + (long long)i*MD*HD;

    #define MSG_BODY(JB, CB, CC) { \
        float l0 = lg[(JB)*4], l1 = lg[(JB)*4+1], l2 = lg[(JB)*4+2], l3 = lg[(JB)*4+3]; \
        float base = base_i + (CB) + (CC); \
        if (l0 > 0.f) acc += fmaxf(fmaf(l0, wt0, base), 0.f); \
        if (l1 > 0.f) acc += fmaxf(fmaf(l1, wt1, base), 0.f); \
        if (l2 > 0.f) acc += fmaxf(fmaf(l2, wt2, base), 0.f); \
        if (l3 > 0.f) acc += fmaxf(fmaf(l3, wt3, base), 0.f); }

    float b0=0,b1=0,b2=0,b3=0,c0=0,c1=0,c2=0,c3=0;
    if (n > 0){ int j=jl[0]; b0=g_Bj[j*HD+h]; c0=CeI[j*HD+h]; }
    if (n > 1){ int j=jl[1]; b1=g_Bj[j*HD+h]; c1=CeI[j*HD+h]; }
    if (n > 2){ int j=jl[2]; b2=g_Bj[j*HD+h]; c2=CeI[j*HD+h]; }
    if (n > 3){ int j=jl[3]; b3=g_Bj[j*HD+h]; c3=CeI[j*HD+h]; }
    int q = 0;
    const int nq = n & ~3;
    for (; q < nq; q += 4){
        float tb0=b0, tc0=c0, tb1=b1, tc1=c1, tb2=b2, tc2=c2, tb3=b3, tc3=c3;
        if (q+4 < n){ int j=jl[q+4]; b0=g_Bj[j*HD+h]; c0=CeI[j*HD+h]; }
        if (q+5 < n){ int j=jl[q+5]; b1=g_Bj[j*HD+h]; c1=CeI[j*HD+h]; }
        if (q+6 < n){ int j=jl[q+6]; b2=g_Bj[j*HD+h]; c2=CeI[j*HD+h]; }
        if (q+7 < n){ int j=jl[q+7]; b3=g_Bj[j*HD+h]; c3=CeI[j*HD+h]; }
        MSG_BODY(jl[q  ], tb0, tc0);
        MSG_BODY(jl[q+1], tb1, tc1);
        MSG_BODY(jl[q+2], tb2, tc2);
        MSG_BODY(jl[q+3], tb3, tc3);
    }
    for (; q < n; q++){
        int j = jl[q];
        float cb = g_Bj[j*HD+h], cc = CeI[j*HD+h];
        MSG_BODY(j, cb, cc);
    }
    #undef MSG_BODY
    childout[i*HD + h] = any ? acc : cin;
}

// ---------------- heads partials with inline h-reduce. grid (9,4,4) ----------------
// h(gm,k) = relu(bc[k] + sum_{z=0..7} g_part[z][gm,k]); child2 partials -> g_part slices 8..11.
__device__ __forceinline__ float hval(int gm, int k, const float* __restrict__ bc){
    float s = 0.f;
    #pragma unroll
    for (int z=0; z<8; z++) s += g_part[(size_t)z*MN + gm*HD + k];
    return fmaxf(s + bc[k], 0.f);
}
__global__ void k_heads(const float* __restrict__ Wc2, const float* __restrict__ Ws,
                        const float* __restrict__ bc){
    __shared__ ull   As2[16*33];
    __shared__ float Bs[16*68];
    const bool semjob = (blockIdx.x == 8);
    const float* B = semjob ? Ws : Wc2;
    const int N   = semjob ? 57 : 512;
    const int n0  = semjob ? 0  : blockIdx.x*64;
    const int m0  = blockIdx.y*32;
    const int kb  = blockIdx.z*128;
    const int t = threadIdx.x, tr = t>>4, tc = t&15;
    const int ar0 = t>>4, ak = t&15, ar1 = ar0+16;
    const int bn = t&63, bk0 = t>>6;
    const int gm0 = m0+ar0, gm1 = m0+ar1;
    const bool bok = (n0 + bn) < N;
    float pa0, pa1, pb0, pb1, pb2, pb3;
    {
        int k = kb + ak;
        pa0 = (gm0 < MD) ? hval(gm0, k, bc) : 0.f;
        pa1 = (gm1 < MD) ? hval(gm1, k, bc) : 0.f;
        int kB = kb + bk0;
        pb0 = bok ? B[(kB   )*N + n0+bn] : 0.f;
        pb1 = bok ? B[(kB+4 )*N + n0+bn] : 0.f;
        pb2 = bok ? B[(kB+8 )*N + n0+bn] : 0.f;
        pb3 = bok ? B[(kB+12)*N + n0+bn] : 0.f;
    }
    ull acc[2][2] = {};
    for (int kt=0; kt<8; kt++){
        As2[ak*33 + ar0] = dup2(pa0);
        As2[ak*33 + ar1] = dup2(pa1);
        Bs[(bk0   )*68 + bn] = pb0;
        Bs[(bk0+4 )*68 + bn] = pb1;
        Bs[(bk0+8 )*68 + bn] = pb2;
        Bs[(bk0+12)*68 + bn] = pb3;
        __syncthreads();
        if (kt+1 < 8){
            int k = kb + (kt+1)*16 + ak;
            pa0 = (gm0 < MD) ? hval(gm0, k, bc) : 0.f;
            pa1 = (gm1 < MD) ? hval(gm1, k, bc) : 0.f;
            int kB = kb + (kt+1)*16 + bk0;
            pb0 = bok ? B[(kB   )*N + n0+bn] : 0.f;
            pb1 = bok ? B[(kB+4 )*N + n0+bn] : 0.f;
            pb2 = bok ? B[(kB+8 )*N + n0+bn] : 0.f;
            pb3 = bok ? B[(kB+12)*N + n0+bn] : 0.f;
        }
        #pragma unroll
        for (int k=0; k<16; k++){
            ull a0 = As2[k*33+tr], a1 = As2[k*33+tr+16];
            float4 bf = *(const float4*)&Bs[k*68 + tc*4];
            ull b0 = ((const ull*)&bf)[0], b1 = ((const ull*)&bf)[1];
            acc[0][0]=ffma2(a0,b0,acc[0][0]); acc[0][1]=ffma2(a0,b1,acc[0][1]);
            acc[1][0]=ffma2(a1,b0,acc[1][0]); acc[1][1]=ffma2(a1,b1,acc[1][1]);
        }
        __syncthreads();
    }
    const int sl = blockIdx.z;
    #pragma unroll
    for (int rr=0; rr<2; rr++){
        int gm = m0 + tr + rr*16;
        if (gm >= MD) continue;
        float r0 = __uint_as_float((unsigned)(acc[rr][0]      ));
        float r1 = __uint_as_float((unsigned)(acc[rr][0] >> 32));
        float r2 = __uint_as_float((unsigned)(acc[rr][1]      ));
        float r3 = __uint_as_float((unsigned)(acc[rr][1] >> 32));
        int gn = n0 + tc*4;
        if (!semjob){
            ull* cp = (ull*)(g_part + (size_t)(8+sl)*MN + gm*HD + gn);
            cp[0] = acc[rr][0]; cp[1] = acc[rr][1];
        } else {
            float* P = g_partS + sl*5700 + gm*57;
            if (gn   < 57) P[gn  ] = r0;
            if (gn+1 < 57) P[gn+1] = r1;
            if (gn+2 < 57) P[gn+2] = r2;
            if (gn+3 < 57) P[gn+3] = r3;
        }
    }
}

// final output reduce. blocks 0..49: child_out float4 (part slices 8..11), 50..72: sem scalar.
__global__ void k_out(const float* __restrict__ bc2, const float* __restrict__ bs,
                      float* __restrict__ out_co, float* __restrict__ out_sem){
    if (blockIdx.x < 50){
        int i4 = blockIdx.x*256 + threadIdx.x;
        const float4* P = (const float4*)g_part;
        float4 s = make_float4(0.f,0.f,0.f,0.f);
        #pragma unroll
        for (int z=0; z<4; z++){
            float4 v = P[(size_t)(8+z)*12800 + i4];
            s.x+=v.x; s.y+=v.y; s.z+=v.z; s.w+=v.w;
        }
        float4 b = ((const float4*)bc2)[i4 & 127];
        s.x = fmaxf(s.x+b.x,0.f); s.y = fmaxf(s.y+b.y,0.f);
        s.z = fmaxf(s.z+b.z,0.f); s.w = fmaxf(s.w+b.w,0.f);
        ((float4*)out_co)[i4] = s;
    } else {
        int e = (blockIdx.x-50)*256 + threadIdx.x;
        if (e >= 5700) return;
        float s = 0.f;
        #pragma unroll
        for (int z=0; z<4; z++) s += g_partS[z*5700 + e];
        out_sem[e] = s + bs[e % 57];
    }
}

// ---------------- launch: 13 kernels ----------------
extern "C" void kernel_launch(void* const* d_in, const int* in_sizes, int n_in,
                              void* d_out, int out_size){
    const float* pf  = (const float*)d_in[0];
    const float* Wp  = (const float*)d_in[1];
    const float* bp  = (const float*)d_in[2];
    const float* Wx  = (const float*)d_in[3];
    const float* bx  = (const float*)d_in[4];
    const float* Wel = (const float*)d_in[5];
    const float* bel = (const float*)d_in[6];
    const float* Wee = (const float*)d_in[7];
    const float* bee = (const float*)d_in[8];
    const float* Wne = (const float*)d_in[9];
    const float* bne = (const float*)d_in[10];
    const float* Wc  = (const float*)d_in[11];
    const float* bc  = (const float*)d_in[12];
    const float* Ws  = (const float*)d_in[13];
    const float* bs  = (const float*)d_in[14];
    const float* Wc2 = (const float*)d_in[15];
    const float* bc2 = (const float*)d_in[16];

    float* out     = (float*)d_out;
    float* out_co  = out;
    float* out_sem = out + 51200;
    float* out_ex  = out + 56900;
    float* out_lg  = out + 57000;

    k_gemv_part<<<dim3(50,4),256>>>(pf, Wp);
    k_gemv_fin<<<100,128>>>(bp, Wx, bx, out_ex);
    k_gp<<<dim3(8,4,16),256>>>(5 | (5<<8) | (5<<16) | (5<<24), 512, 4,
                               Wel, Wel + 512*512, Wne, Wne + 512*512);
    k_red<<<200,256>>>(4, 4, 0, 1, 2, 3);
    k_el<<<dim3(100,13),256>>>(bel, Wee, bee, out_lg);
    k_ce<<<dim3(8,157),256>>>(Wne + 1024*512, Wne + (1540+1024)*512, bel);
    k_msg<<<100,512>>>(0, out_lg, Wne + 1536*512, bne);
    k_gp<<<dim3(8,4,8),256>>>(6 | (6<<8), 512, 4,
                              Wne + 1540*512, Wne + (1540+512)*512, Wne, Wne);
    k_red<<<100,256>>>(4, 2, 2, 3, 0, 0);
    k_msg<<<100,512>>>(1, out_lg, Wne + (1540+1536)*512, bne + 512);
    k_gp<<<dim3(8,4,8),256>>>(9, 1536, 8, Wc, Wc, Wc, Wc);
    k_heads<<<dim3(9,4,4),256>>>(Wc2, Ws, bc);
    k_out<<<73,256>>>(bc2, bs, out_co, out_sem);
}

// round 14
// speedup vs baseline: 1.1214x; 1.0608x over previous
#include <cuda_runtime.h>

typedef unsigned long long ull;

#define MD 100
#define HD 512
#define NP 10000
#define MN 51200

// ---------------- device scratch ----------------
__device__ __align__(16) float g_child0[MD*HD];
__device__ __align__(16) float g_child1[MD*HD];
__device__ __align__(16) float g_child2[MD*HD];
__device__ __align__(16) float g_A[MD*HD];
__device__ __align__(16) float g_B[MD*HD];
__device__ __align__(16) float g_Ai[MD*HD];
__device__ __align__(16) float g_Bj[MD*HD];
__device__ __align__(16) float g_Ce0[NP*HD];
__device__ __align__(16) float g_Ce1[NP*HD];
__device__ __align__(16) float g_gpart[4*MN];
__device__ __align__(16) float g_part[16*MN];
__device__ __align__(16) float g_partS[4*5700];
__device__ int   g_nodeok[MD];
__device__ int   g_pairlist[NP];
__device__ int   g_paircnt;

__device__ __forceinline__ ull ffma2(ull a, ull b, ull c){
    ull d;
    asm("fma.rn.f32x2 %0, %1, %2, %3;" : "=l"(d) : "l"(a), "l"(b), "l"(c));
    return d;
}
__device__ __forceinline__ ull dup2(float v){
    unsigned u = __float_as_uint(v);
    return ((ull)u << 32) | (ull)u;
}
__device__ __forceinline__ unsigned tf32_rna(float v){
    unsigned r;
    asm("cvt.rna.tf32.f32 %0, %1;" : "=r"(r) : "f"(v));
    return r;
}
__device__ __forceinline__ void mma_tf32(float4& d, unsigned a0, unsigned a1,
                                         unsigned a2, unsigned a3,
                                         unsigned b0, unsigned b1){
    asm volatile("mma.sync.aligned.m16n8k8.row.col.f32.tf32.tf32.f32 "
                 "{%0,%1,%2,%3}, {%4,%5,%6,%7}, {%8,%9}, {%0,%1,%2,%3};"
                 : "+f"(d.x), "+f"(d.y), "+f"(d.z), "+f"(d.w)
                 : "r"(a0), "r"(a1), "r"(a2), "r"(a3), "r"(b0), "r"(b1));
}
__device__ __forceinline__ float* sel_buf(int code){
    switch (code){
        case 0: return g_A;      case 1: return g_B;
        case 2: return g_Ai;     case 3: return g_Bj;
        case 4: return g_part;   case 5: return g_child0;
        case 6: return g_child1; default: return g_child2;
    }
}
__device__ __forceinline__ float fetchA(int code, int m, int k){
    if (code == 9){   // virtual concat [child0|child1|child2]
        int q = k >> 9, kk = k & 511;
        const float* s = (q==0) ? g_child0 : (q==1) ? g_child1 : g_child2;
        return s[m*HD + kk];
    }
    return sel_buf(code)[m*HD + k];
}

// ---------------- parent GEMV: float4, split-K. grid (50,4), 256 thr ----------------
__global__ void k_gemv_part(const float* __restrict__ pf, const float* __restrict__ Wp){
    __shared__ float pfs[128];
    const int z = blockIdx.y;
    const int c4 = blockIdx.x*256 + threadIdx.x;
    if (threadIdx.x < 128) pfs[threadIdx.x] = pf[z*128 + threadIdx.x];
    __syncthreads();
    const float4* w = (const float4*)Wp + (long long)(z*128)*12800 + c4;
    float4 a = make_float4(0.f,0.f,0.f,0.f);
    #pragma unroll 8
    for (int k=0; k<128; k++){
        float4 wv = w[(long long)k*12800];
        float s = pfs[k];
        a.x += s*wv.x; a.y += s*wv.y; a.z += s*wv.z; a.w += s*wv.w;
    }
    ((float4*)g_gpart)[z*12800 + c4] = a;
}

// finisher + exists logits fused. grid 100, 128 thr.
__global__ void k_gemv_fin(const float* __restrict__ bp, const float* __restrict__ Wx,
                           const float* __restrict__ bx, float* __restrict__ out_ex){
    __shared__ float red[4];
    const int m = blockIdx.x, t = threadIdx.x;
    const int c4 = m*128 + t;
    const float4* gp = (const float4*)g_gpart;
    float4 s0 = gp[c4], s1 = gp[12800+c4], s2 = gp[2*12800+c4], s3 = gp[3*12800+c4];
    float4 b  = ((const float4*)bp)[c4];
    float4 v;
    v.x = fmaxf(s0.x+s1.x+s2.x+s3.x+b.x, 0.f);
    v.y = fmaxf(s0.y+s1.y+s2.y+s3.y+b.y, 0.f);
    v.z = fmaxf(s0.z+s1.z+s2.z+s3.z+b.z, 0.f);
    v.w = fmaxf(s0.w+s1.w+s2.w+s3.w+b.w, 0.f);
    ((float4*)g_child0)[c4] = v;
    float4 wx = ((const float4*)Wx)[t];
    float p = v.x*wx.x + v.y*wx.y + v.z*wx.z + v.w*wx.w;
    #pragma unroll
    for (int o=16; o; o>>=1) p += __shfl_xor_sync(~0u, p, o);
    if ((t & 31) == 0) red[t>>5] = p;
    __syncthreads();
    if (t == 0){
        float vv = red[0]+red[1]+red[2]+red[3] + bx[0];
        out_ex[m]   = vv;
        g_nodeok[m] = (vv > 0.f) ? 1 : 0;
        if (m == 0) g_paircnt = 0;
    }
}

// ---------------- split-K multi-job GEMM partials, pipelined ----------------
__global__ void k_gp(int acodes, int Klen, int KS,
                     const float* __restrict__ B0, const float* __restrict__ B1,
                     const float* __restrict__ B2, const float* __restrict__ B3){
    __shared__ ull   As2[16*33];
    __shared__ float Bs[16*68];
    const int KSL = Klen / KS;
    const int job = blockIdx.z / KS, sl = blockIdx.z % KS;
    const int Acode = (acodes >> (8*job)) & 255;
    const float* B = (job==0)?B0:(job==1)?B1:(job==2)?B2:B3;
    const int kb = sl*KSL;
    const int n0 = blockIdx.x*64, m0 = blockIdx.y*32;
    const int t = threadIdx.x, tr = t>>4, tc = t&15;
    const int ar0 = t>>4, ak = t&15, ar1 = ar0+16;
    const int bn = t&63, bk0 = t>>6;
    const int gm0 = m0+ar0, gm1 = m0+ar1;
    float pa0, pa1, pb0, pb1, pb2, pb3;
    {
        int k = kb + ak;
        pa0 = (gm0 < MD) ? fetchA(Acode, gm0, k) : 0.f;
        pa1 = (gm1 < MD) ? fetchA(Acode, gm1, k) : 0.f;
        int kB = kb + bk0;
        pb0 = B[(kB   )*HD + n0+bn]; pb1 = B[(kB+4 )*HD + n0+bn];
        pb2 = B[(kB+8 )*HD + n0+bn]; pb3 = B[(kB+12)*HD + n0+bn];
    }
    ull acc[2][2] = {};
    const int nkt = KSL/16;
    for (int kt=0; kt<nkt; kt++){
        As2[ak*33 + ar0] = dup2(pa0);
        As2[ak*33 + ar1] = dup2(pa1);
        Bs[(bk0   )*68 + bn] = pb0;
        Bs[(bk0+4 )*68 + bn] = pb1;
        Bs[(bk0+8 )*68 + bn] = pb2;
        Bs[(bk0+12)*68 + bn] = pb3;
        __syncthreads();
        if (kt+1 < nkt){
            int k = kb + (kt+1)*16 + ak;
            pa0 = (gm0 < MD) ? fetchA(Acode, gm0, k) : 0.f;
            pa1 = (gm1 < MD) ? fetchA(Acode, gm1, k) : 0.f;
            int kB = kb + (kt+1)*16 + bk0;
            pb0 = B[(kB   )*HD + n0+bn]; pb1 = B[(kB+4 )*HD + n0+bn];
            pb2 = B[(kB+8 )*HD + n0+bn]; pb3 = B[(kB+12)*HD + n0+bn];
        }
        #pragma unroll
        for (int k=0; k<16; k++){
            ull a0 = As2[k*33+tr], a1 = As2[k*33+tr+16];
            float4 bf = *(const float4*)&Bs[k*68 + tc*4];
            ull b0 = ((const ull*)&bf)[0], b1 = ((const ull*)&bf)[1];
            acc[0][0]=ffma2(a0,b0,acc[0][0]); acc[0][1]=ffma2(a0,b1,acc[0][1]);
            acc[1][0]=ffma2(a1,b0,acc[1][0]); acc[1][1]=ffma2(a1,b1,acc[1][1]);
        }
        __syncthreads();
    }
    float* P = g_part + (size_t)blockIdx.z*MN;
    #pragma unroll
    for (int rr=0; rr<2; rr++){
        int gm = m0 + tr + rr*16;
        if (gm < MD){
            ull* cp = (ull*)(P + gm*HD + n0 + tc*4);
            cp[0] = acc[rr][0]; cp[1] = acc[rr][1];
        }
    }
}

// sum S slices per job (float4)
__global__ void k_red(int S, int njobs, int d0, int d1, int d2, int d3){
    int i4 = blockIdx.x*256 + threadIdx.x;
    if (i4 >= njobs*12800) return;
    int job = i4 / 12800, e4 = i4 - job*12800;
    const float4* P = (const float4*)g_part;
    float4 s = make_float4(0.f,0.f,0.f,0.f);
    for (int z=0; z<S; z++){
        float4 v = P[(size_t)(job*S+z)*12800 + e4];
        s.x+=v.x; s.y+=v.y; s.z+=v.z; s.w+=v.w;
    }
    int dc = (job==0)?d0:(job==1)?d1:(job==2)?d2:d3;
    ((float4*)sel_buf(dc))[e4] = s;
}

// ---------------- edge logits + pair compaction. grid (100,13), 256 thr ----------------
__global__ void k_el(const float* __restrict__ bel, const float* __restrict__ Wee,
                     const float* __restrict__ bee, float* __restrict__ out_lg){
    __shared__ float sWee[4*HD];
    __shared__ float sbel[HD];
    const int t = threadIdx.x;
    #pragma unroll
    for (int q=0; q<8; q++) sWee[t + q*256] = Wee[t + q*256];
    sbel[t] = bel[t]; sbel[t+256] = bel[t+256];
    __syncthreads();
    const int i = blockIdx.x;
    const int w = t >> 5, lane = t & 31;
    const int j = blockIdx.y*8 + w;
    if (j >= MD) return;
    const float* Ar = g_A + i*HD;
    const float* Br = g_B + j*HD;
    float p0=0.f, p1=0.f, p2=0.f, p3=0.f;
    #pragma unroll
    for (int s=0; s<16; s++){
        int h = lane + s*32;
        float v = fmaxf(Ar[h] + Br[h] + sbel[h], 0.f);
        p0 += v*sWee[h]; p1 += v*sWee[HD+h]; p2 += v*sWee[2*HD+h]; p3 += v*sWee[3*HD+h];
    }
    #pragma unroll
    for (int o=16; o; o>>=1){
        p0 += __shfl_xor_sync(~0u, p0, o);
        p1 += __shfl_xor_sync(~0u, p1, o);
        p2 += __shfl_xor_sync(~0u, p2, o);
        p3 += __shfl_xor_sync(~0u, p3, o);
    }
    if (lane == 0){
        p0 += bee[0]; p1 += bee[1]; p2 += bee[2]; p3 += bee[3];
        int p = i*MD + j;
        *(float4*)(out_lg + p*4) = make_float4(p0, p1, p2, p3);
        if (g_nodeok[i] && g_nodeok[j] && (p0>0.f || p1>0.f || p2>0.f || p3>0.f)){
            int pos = atomicAdd(&g_paircnt, 1);
            g_pairlist[pos] = p;
        }
    }
}

// ---------------- gathered edge GEMM via TF32 tensor cores (3xTF32 split) ----------------
// grid (8,157), 256 thr = 8 warps. Tile 64 pairs x 64 cols, BOTH iterations.
// Warp w: M-half mw = w&1 (32 rows), N-quarter nw = w>>1 (16 cols).
// smem stores {hi,lo} float2 per element; fragments load as single LDS.64.
__global__ void k_ce(const float* __restrict__ We0, const float* __restrict__ We1,
                     const float* __restrict__ bel){
    __shared__ int   pp[64], pi[64], pj[64];
    __shared__ float sbel[HD];
    __shared__ __align__(16) float2 As [16*68];   // [k][row]
    __shared__ __align__(16) float2 Bs0[16*68];   // [k][n]
    __shared__ __align__(16) float2 Bs1[16*68];
    const int cnt = g_paircnt;
    const int m0  = blockIdx.y*64;
    if (m0 >= cnt) return;
    const int n0 = blockIdx.x*64;
    const int t = threadIdx.x;
    if (t < 64){
        int p = (m0 + t < cnt) ? g_pairlist[m0 + t] : g_pairlist[m0];
        pp[t] = p; pi[t] = (p/MD)*HD; pj[t] = (p%MD)*HD;
    }
    sbel[t] = bel[t]; sbel[t+256] = bel[t+256];
    __syncthreads();
    // loader mappings
    const int lr  = t & 63, lk4 = (t >> 6)*4;     // A: row, 4 consecutive k
    const int bk  = t >> 4, bn4 = (t & 15)*4;     // B: k-row, 4 consecutive n
    const int piR = pi[lr], pjR = pj[lr];
    // warp/mma mappings
    const int w = t >> 5, lane = t & 31;
    const int mw = w & 1, nw = w >> 1;
    const int g  = lane >> 2, ctg = lane & 3;
    float4 va, vb, w0, w1;
    va = *(const float4*)&g_A[piR + lk4];
    vb = *(const float4*)&g_B[pjR + lk4];
    w0 = *(const float4*)&We0[bk*HD + n0 + bn4];
    w1 = *(const float4*)&We1[bk*HD + n0 + bn4];
    float4 acc[2][2][2];   // [iter][mt][nt]
    #pragma unroll
    for (int i1=0;i1<2;i1++)
        #pragma unroll
        for (int i2=0;i2<2;i2++)
            #pragma unroll
            for (int i3=0;i3<2;i3++) acc[i1][i2][i3] = make_float4(0.f,0.f,0.f,0.f);
    for (int kt=0; kt<32; kt++){
        {   // split + stage current tile
            const int kb2 = kt*16;
            float v0 = fmaxf(va.x + vb.x + sbel[kb2 + lk4    ], 0.f);
            float v1 = fmaxf(va.y + vb.y + sbel[kb2 + lk4 + 1], 0.f);
            float v2 = fmaxf(va.z + vb.z + sbel[kb2 + lk4 + 2], 0.f);
            float v3 = fmaxf(va.w + vb.w + sbel[kb2 + lk4 + 3], 0.f);
            float h0 = __uint_as_float(tf32_rna(v0));
            float h1 = __uint_as_float(tf32_rna(v1));
            float h2 = __uint_as_float(tf32_rna(v2));
            float h3 = __uint_as_float(tf32_rna(v3));
            As[(lk4  )*68 + lr] = make_float2(h0, __uint_as_float(tf32_rna(v0-h0)));
            As[(lk4+1)*68 + lr] = make_float2(h1, __uint_as_float(tf32_rna(v1-h1)));
            As[(lk4+2)*68 + lr] = make_float2(h2, __uint_as_float(tf32_rna(v2-h2)));
            As[(lk4+3)*68 + lr] = make_float2(h3, __uint_as_float(tf32_rna(v3-h3)));
            float b0h = __uint_as_float(tf32_rna(w0.x));
            float b1h = __uint_as_float(tf32_rna(w0.y));
            float b2h = __uint_as_float(tf32_rna(w0.z));
            float b3h = __uint_as_float(tf32_rna(w0.w));
            float4* bp0 = (float4*)&Bs0[bk*68 + bn4];
            bp0[0] = make_float4(b0h, __uint_as_float(tf32_rna(w0.x-b0h)),
                                 b1h, __uint_as_float(tf32_rna(w0.y-b1h)));
            bp0[1] = make_float4(b2h, __uint_as_float(tf32_rna(w0.z-b2h)),
                                 b3h, __uint_as_float(tf32_rna(w0.w-b3h)));
            float c0h = __uint_as_float(tf32_rna(w1.x));
            float c1h = __uint_as_float(tf32_rna(w1.y));
            float c2h = __uint_as_float(tf32_rna(w1.z));
            float c3h = __uint_as_float(tf32_rna(w1.w));
            float4* bp1 = (float4*)&Bs1[bk*68 + bn4];
            bp1[0] = make_float4(c0h, __uint_as_float(tf32_rna(w1.x-c0h)),
                                 c1h, __uint_as_float(tf32_rna(w1.y-c1h)));
            bp1[1] = make_float4(c2h, __uint_as_float(tf32_rna(w1.z-c2h)),
                                 c3h, __uint_as_float(tf32_rna(w1.w-c3h)));
        }
        __syncthreads();
        if (kt+1 < 32){
            int ko = (kt+1)*16;
            va = *(const float4*)&g_A[piR + ko + lk4];
            vb = *(const float4*)&g_B[pjR + ko + lk4];
            w0 = *(const float4*)&We0[(ko + bk)*HD + n0 + bn4];
            w1 = *(const float4*)&We1[(ko + bk)*HD + n0 + bn4];
        }
        #pragma unroll
        for (int ks=0; ks<16; ks+=8){
            // A fragments for the two m16 tiles
            float2 af[2][4];
            #pragma unroll
            for (int mt=0; mt<2; mt++){
                int mo = mw*32 + mt*16;
                af[mt][0] = As[(ks+ctg  )*68 + mo + g];
                af[mt][1] = As[(ks+ctg  )*68 + mo + g + 8];
                af[mt][2] = As[(ks+ctg+4)*68 + mo + g];
                af[mt][3] = As[(ks+ctg+4)*68 + mo + g + 8];
            }
            #pragma unroll
            for (int it=0; it<2; it++){
                const float2* Bsm = it ? Bs1 : Bs0;
                #pragma unroll
                for (int nt=0; nt<2; nt++){
                    int no = nw*16 + nt*8;
                    float2 bf0 = Bsm[(ks+ctg  )*68 + no + g];
                    float2 bf1 = Bsm[(ks+ctg+4)*68 + no + g];
                    unsigned bh0 = __float_as_uint(bf0.x), bh1 = __float_as_uint(bf1.x);
                    unsigned bl0 = __float_as_uint(bf0.y), bl1 = __float_as_uint(bf1.y);
                    #pragma unroll
                    for (int mt=0; mt<2; mt++){
                        unsigned ah0 = __float_as_uint(af[mt][0].x);
                        unsigned ah1 = __float_as_uint(af[mt][1].x);
                        unsigned ah2 = __float_as_uint(af[mt][2].x);
                        unsigned ah3 = __float_as_uint(af[mt][3].x);
                        unsigned al0 = __float_as_uint(af[mt][0].y);
                        unsigned al1 = __float_as_uint(af[mt][1].y);
                        unsigned al2 = __float_as_uint(af[mt][2].y);
                        unsigned al3 = __float_as_uint(af[mt][3].y);
                        float4& d = acc[it][mt][nt];
                        mma_tf32(d, ah0, ah1, ah2, ah3, bh0, bh1);   // hi*hi
                        mma_tf32(d, ah0, ah1, ah2, ah3, bl0, bl1);   // hi*lo
                        mma_tf32(d, al0, al1, al2, al3, bh0, bh1);   // lo*hi
                    }
                }
            }
        }
        __syncthreads();
    }
    // epilogue: per tile, lane stores (row g, cols 2*ctg..+1) and (row g+8)
    #pragma unroll
    for (int it=0; it<2; it++){
        float* C = it ? g_Ce1 : g_Ce0;
        #pragma unroll
        for (int mt=0; mt<2; mt++){
            #pragma unroll
            for (int nt=0; nt<2; nt++){
                float4 d = acc[it][mt][nt];
                int rl0 = mw*32 + mt*16 + g;
                int col = n0 + nw*16 + nt*8 + ctg*2;
                if (m0 + rl0 < cnt){
                    float* p = C + pp[rl0]*HD + col;
                    p[0] = d.x; p[1] = d.y;
                }
                int rl1 = rl0 + 8;
                if (m0 + rl1 < cnt){
                    float* p = C + pp[rl1]*HD + col;
                    p[0] = d.z; p[1] = d.w;
                }
            }
        }
    }
}

// ---------------- message pass + scatter-sum. grid 100, 512 thr, 4-deep prefetch ----------------
__global__ void k_msg(int it, const float* __restrict__ lgg,
                      const float* __restrict__ Wt, const float* __restrict__ bne){
    __shared__ float lg[400];
    __shared__ int   jl[100];
    __shared__ int   njl;
    const float* childin  = it ? g_child1 : g_child0;
    float*       childout = it ? g_child2 : g_child1;
    const float* Ce       = it ? g_Ce1    : g_Ce0;
    const int i = blockIdx.x, h = threadIdx.x;
    if (h < 400) lg[h] = lgg[i*400 + h];
    __syncthreads();
    if (h == 0){
        int n = 0;
        if (g_nodeok[i]){
            for (int j=0; j<MD; j++){
                if (!g_nodeok[j]) continue;
                if (lg[j*4]>0.f || lg[j*4+1]>0.f || lg[j*4+2]>0.f || lg[j*4+3]>0.f) jl[n++] = j;
            }
        }
        njl = n;
    }
    __syncthreads();
    float cin = childin[i*HD + h];
    bool any = (g_paircnt > 0);
    float acc = 0.f;
    const int n = njl;
    float base_i = g_Ai[i*HD + h] + bne[h];
    float wt0 = Wt[h], wt1 = Wt[HD+h], wt2 = Wt[2*HD+h], wt3 = Wt[3*HD+h];
    const float* CeI = Ce + (long long)i*MD*HD;

    #define MSG_BODY(JB, CB, CC) { \
        float l0 = lg[(JB)*4], l1 = lg[(JB)*4+1], l2 = lg[(JB)*4+2], l3 = lg[(JB)*4+3]; \
        float base = base_i + (CB) + (CC); \
        if (l0 > 0.f) acc += fmaxf(fmaf(l0, wt0, base), 0.f); \
        if (l1 > 0.f) acc += fmaxf(fmaf(l1, wt1, base), 0.f); \
        if (l2 > 0.f) acc += fmaxf(fmaf(l2, wt2, base), 0.f); \
        if (l3 > 0.f) acc += fmaxf(fmaf(l3, wt3, base), 0.f); }

    float b0=0,b1=0,b2=0,b3=0,c0=0,c1=0,c2=0,c3=0;
    if (n > 0){ int j=jl[0]; b0=g_Bj[j*HD+h]; c0=CeI[j*HD+h]; }
    if (n > 1){ int j=jl[1]; b1=g_Bj[j*HD+h]; c1=CeI[j*HD+h]; }
    if (n > 2){ int j=jl[2]; b2=g_Bj[j*HD+h]; c2=CeI[j*HD+h]; }
    if (n > 3){ int j=jl[3]; b3=g_Bj[j*HD+h]; c3=CeI[j*HD+h]; }
    int q = 0;
    const int nq = n & ~3;
    for (; q < nq; q += 4){
        float tb0=b0, tc0=c0, tb1=b1, tc1=c1, tb2=b2, tc2=c2, tb3=b3, tc3=c3;
        if (q+4 < n){ int j=jl[q+4]; b0=g_Bj[j*HD+h]; c0=CeI[j*HD+h]; }
        if (q+5 < n){ int j=jl[q+5]; b1=g_Bj[j*HD+h]; c1=CeI[j*HD+h]; }
        if (q+6 < n){ int j=jl[q+6]; b2=g_Bj[j*HD+h]; c2=CeI[j*HD+h]; }
        if (q+7 < n){ int j=jl[q+7]; b3=g_Bj[j*HD+h]; c3=CeI[j*HD+h]; }
        MSG_BODY(jl[q  ], tb0, tc0);
        MSG_BODY(jl[q+1], tb1, tc1);
        MSG_BODY(jl[q+2], tb2, tc2);
        MSG_BODY(jl[q+3], tb3, tc3);
    }
    for (; q < n; q++){
        int j = jl[q];
        float cb = g_Bj[j*HD+h], cc = CeI[j*HD+h];
        MSG_BODY(j, cb, cc);
    }
    #undef MSG_BODY
    childout[i*HD + h] = any ? acc : cin;
}

// ---------------- heads partials with inline h-reduce. grid (9,4,4) ----------------
__device__ __forceinline__ float hval(int gm, int k, const float* __restrict__ bc){
    float s = 0.f;
    #pragma unroll
    for (int z=0; z<8; z++) s += g_part[(size_t)z*MN + gm*HD + k];
    return fmaxf(s + bc[k], 0.f);
}
__global__ void k_heads(const float* __restrict__ Wc2, const float* __restrict__ Ws,
                        const float* __restrict__ bc){
    __shared__ ull   As2[16*33];
    __shared__ float Bs[16*68];
    const bool semjob = (blockIdx.x == 8);
    const float* B = semjob ? Ws : Wc2;
    const int N   = semjob ? 57 : 512;
    const int n0  = semjob ? 0  : blockIdx.x*64;
    const int m0  = blockIdx.y*32;
    const int kb  = blockIdx.z*128;
    const int t = threadIdx.x, tr = t>>4, tc = t&15;
    const int ar0 = t>>4, ak = t&15, ar1 = ar0+16;
    const int bn = t&63, bk0 = t>>6;
    const int gm0 = m0+ar0, gm1 = m0+ar1;
    const bool bok = (n0 + bn) < N;
    float pa0, pa1, pb0, pb1, pb2, pb3;
    {
        int k = kb + ak;
        pa0 = (gm0 < MD) ? hval(gm0, k, bc) : 0.f;
        pa1 = (gm1 < MD) ? hval(gm1, k, bc) : 0.f;
        int kB = kb + bk0;
        pb0 = bok ? B[(kB   )*N + n0+bn] : 0.f;
        pb1 = bok ? B[(kB+4 )*N + n0+bn] : 0.f;
        pb2 = bok ? B[(kB+8 )*N + n0+bn] : 0.f;
        pb3 = bok ? B[(kB+12)*N + n0+bn] : 0.f;
    }
    ull acc[2][2] = {};
    for (int kt=0; kt<8; kt++){
        As2[ak*33 + ar0] = dup2(pa0);
        As2[ak*33 + ar1] = dup2(pa1);
        Bs[(bk0   )*68 + bn] = pb0;
        Bs[(bk0+4 )*68 + bn] = pb1;
        Bs[(bk0+8 )*68 + bn] = pb2;
        Bs[(bk0+12)*68 + bn] = pb3;
        __syncthreads();
        if (kt+1 < 8){
            int k = kb + (kt+1)*16 + ak;
            pa0 = (gm0 < MD) ? hval(gm0, k, bc) : 0.f;
            pa1 = (gm1 < MD) ? hval(gm1, k, bc) : 0.f;
            int kB = kb + (kt+1)*16 + bk0;
            pb0 = bok ? B[(kB   )*N + n0+bn] : 0.f;
            pb1 = bok ? B[(kB+4 )*N + n0+bn] : 0.f;
            pb2 = bok ? B[(kB+8 )*N + n0+bn] : 0.f;
            pb3 = bok ? B[(kB+12)*N + n0+bn] : 0.f;
        }
        #pragma unroll
        for (int k=0; k<16; k++){
            ull a0 = As2[k*33+tr], a1 = As2[k*33+tr+16];
            float4 bf = *(const float4*)&Bs[k*68 + tc*4];
            ull b0 = ((const ull*)&bf)[0], b1 = ((const ull*)&bf)[1];
            acc[0][0]=ffma2(a0,b0,acc[0][0]); acc[0][1]=ffma2(a0,b1,acc[0][1]);
            acc[1][0]=ffma2(a1,b0,acc[1][0]); acc[1][1]=ffma2(a1,b1,acc[1][1]);
        }
        __syncthreads();
    }
    const int sl = blockIdx.z;
    #pragma unroll
    for (int rr=0; rr<2; rr++){
        int gm = m0 + tr + rr*16;
        if (gm >= MD) continue;
        float r0 = __uint_as_float((unsigned)(acc[rr][0]      ));
        float r1 = __uint_as_float((unsigned)(acc[rr][0] >> 32));
        float r2 = __uint_as_float((unsigned)(acc[rr][1]      ));
        float r3 = __uint_as_float((unsigned)(acc[rr][1] >> 32));
        int gn = n0 + tc*4;
        if (!semjob){
            ull* cp = (ull*)(g_part + (size_t)(8+sl)*MN + gm*HD + gn);
            cp[0] = acc[rr][0]; cp[1] = acc[rr][1];
        } else {
            float* P = g_partS + sl*5700 + gm*57;
            if (gn   < 57) P[gn  ] = r0;
            if (gn+1 < 57) P[gn+1] = r1;
            if (gn+2 < 57) P[gn+2] = r2;
            if (gn+3 < 57) P[gn+3] = r3;
        }
    }
}

// final output reduce. blocks 0..49: child_out float4 (part slices 8..11), 50..72: sem scalar.
__global__ void k_out(const float* __restrict__ bc2, const float* __restrict__ bs,
                      float* __restrict__ out_co, float* __restrict__ out_sem){
    if (blockIdx.x < 50){
        int i4 = blockIdx.x*256 + threadIdx.x;
        const float4* P = (const float4*)g_part;
        float4 s = make_float4(0.f,0.f,0.f,0.f);
        #pragma unroll
        for (int z=0; z<4; z++){
            float4 v = P[(size_t)(8+z)*12800 + i4];
            s.x+=v.x; s.y+=v.y; s.z+=v.z; s.w+=v.w;
        }
        float4 b = ((const float4*)bc2)[i4 & 127];
        s.x = fmaxf(s.x+b.x,0.f); s.y = fmaxf(s.y+b.y,0.f);
        s.z = fmaxf(s.z+b.z,0.f); s.w = fmaxf(s.w+b.w,0.f);
        ((float4*)out_co)[i4] = s;
    } else {
        int e = (blockIdx.x-50)*256 + threadIdx.x;
        if (e >= 5700) return;
        float s = 0.f;
        #pragma unroll
        for (int z=0; z<4; z++) s += g_partS[z*5700 + e];
        out_sem[e] = s + bs[e % 57];
    }
}

// ---------------- launch: 13 kernels ----------------
extern "C" void kernel_launch(void* const* d_in, const int* in_sizes, int n_in,
                              void* d_out, int out_size){
    const float* pf  = (const float*)d_in[0];
    const float* Wp  = (const float*)d_in[1];
    const float* bp  = (const float*)d_in[2];
    const float* Wx  = (const float*)d_in[3];
    const float* bx  = (const float*)d_in[4];
    const float* Wel = (const float*)d_in[5];
    const float* bel = (const float*)d_in[6];
    const float* Wee = (const float*)d_in[7];
    const float* bee = (const float*)d_in[8];
    const float* Wne = (const float*)d_in[9];
    const float* bne = (const float*)d_in[10];
    const float* Wc  = (const float*)d_in[11];
    const float* bc  = (const float*)d_in[12];
    const float* Ws  = (const float*)d_in[13];
    const float* bs  = (const float*)d_in[14];
    const float* Wc2 = (const float*)d_in[15];
    const float* bc2 = (const float*)d_in[16];

    float* out     = (float*)d_out;
    float* out_co  = out;
    float* out_sem = out + 51200;
    float* out_ex  = out + 56900;
    float* out_lg  = out + 57000;

    k_gemv_part<<<dim3(50,4),256>>>(pf, Wp);
    k_gemv_fin<<<100,128>>>(bp, Wx, bx, out_ex);
    k_gp<<<dim3(8,4,16),256>>>(5 | (5<<8) | (5<<16) | (5<<24), 512, 4,
                               Wel, Wel + 512*512, Wne, Wne + 512*512);
    k_red<<<200,256>>>(4, 4, 0, 1, 2, 3);
    k_el<<<dim3(100,13),256>>>(bel, Wee, bee, out_lg);
    k_ce<<<dim3(8,157),256>>>(Wne + 1024*512, Wne + (1540+1024)*512, bel);
    k_msg<<<100,512>>>(0, out_lg, Wne + 1536*512, bne);
    k_gp<<<dim3(8,4,8),256>>>(6 | (6<<8), 512, 4,
                              Wne + 1540*512, Wne + (1540+512)*512, Wne, Wne);
    k_red<<<100,256>>>(4, 2, 2, 3, 0, 0);
    k_msg<<<100,512>>>(1, out_lg, Wne + (1540+1536)*512, bne + 512);
    k_gp<<<dim3(8,4,8),256>>>(9, 1536, 8, Wc, Wc, Wc, Wc);
    k_heads<<<dim3(9,4,4),256>>>(Wc2, Ws, bc);
    k_out<<<73,256>>>(bc2, bs, out_co, out_sem);
}